// round 5
// baseline (speedup 1.0000x reference)
#include <cuda_runtime.h>

#define BB 128
#define CC 49
#define NN 3136
#define PP 49
#define ICH 7
#define KS 7

// ---------------- scratch (device globals; no allocation) ----------------
__device__ float    g_v[BB * NN];               // v[b][n]
__device__ float    g_qp[ICH * BB * CC * PP];   // q partials [ic][b][c*49+p]
__device__ float    g_qw[BB * CC * CC];         // qw[b][c*49+i]
__device__ float    g_qb[BB * CC];              // qb[b][c]
__device__ unsigned g_amax[BB * CC];            // encoded running max
__device__ float    g_pvp[KS * NN * BB];        // pv partials [ks][m][b]

__device__ __forceinline__ unsigned enc(float f) {
    unsigned u = __float_as_uint(f);
    return (u & 0x80000000u) ? ~u : (u | 0x80000000u);
}
__device__ __forceinline__ float dec(unsigned u) {
    return __uint_as_float((u & 0x80000000u) ? (u & 0x7fffffffu) : ~u);
}

// ---------------- K0: reset max accumulators (every replay) ----------------
__global__ void k_init() {
    int t = blockIdx.x * blockDim.x + threadIdx.x;
    if (t < BB * CC) g_amax[t] = 0u;
}

// ---------------- K2: q-conv partials --------------------------------------
// q[b,c,p] = sum_i sum_dd Wq[c,i,dd] * x[b,i,patch(p,dd)]
// grid (ICH, BB), 96 threads; thread tile 4c x 8p. Direct gmem->xpat repack.
__global__ void __launch_bounds__(96, 6)
k_q(const float* __restrict__ x, const float* __restrict__ Wq) {
    __shared__ __align__(16) float xpat[64 * 52 + 8];  // [dd][p], row pad 52
    __shared__ __align__(16) float wt[52 * 65];        // Wq[c][dd] rows pad 65

    int ic = blockIdx.x, b = blockIdx.y;
    int t = threadIdx.x;
    int cc = t % 13, pg = t / 13;        // active when pg < 7 (91 threads)
    int c0 = cc * 4, p0 = pg * 8;

    float acc[4][8];
#pragma unroll
    for (int j = 0; j < 4; j++)
#pragma unroll
        for (int k = 0; k < 8; k++) acc[j][k] = 0.f;

    for (int ii = 0; ii < 7; ii++) {
        int i = ic * 7 + ii;
        __syncthreads();
        // coalesced read of the channel; permuted scatter into [dd][p]
        const float* xc = x + (b * CC + i) * NN;
        for (int e = t; e < NN; e += 96) {
            int y = e / 56, xx = e - y * 56;
            int py = y >> 3, dy = y & 7, px = xx >> 3, dx = xx & 7;
            xpat[(dy * 8 + dx) * 52 + py * 7 + px] = xc[e];
        }
        for (int e = t; e < CC * 64; e += 96) {
            int c = e >> 6, dd = e & 63;
            wt[c * 65 + dd] = Wq[(c * CC + i) * 64 + dd];
        }
        __syncthreads();
        if (pg < 7) {
#pragma unroll 8
            for (int dd = 0; dd < 64; dd++) {
                float4 xa = *(const float4*)&xpat[dd * 52 + p0];
                float4 xb = *(const float4*)&xpat[dd * 52 + p0 + 4];
#pragma unroll
                for (int j = 0; j < 4; j++) {
                    float w = wt[(c0 + j) * 65 + dd];
                    acc[j][0] += w * xa.x; acc[j][1] += w * xa.y;
                    acc[j][2] += w * xa.z; acc[j][3] += w * xa.w;
                    acc[j][4] += w * xb.x; acc[j][5] += w * xb.y;
                    acc[j][6] += w * xb.z; acc[j][7] += w * xb.w;
                }
            }
        }
    }
    if (pg < 7) {
        float* dst = &g_qp[(ic * BB + b) * CC * PP];
#pragma unroll
        for (int j = 0; j < 4; j++) {
            int c = c0 + j;
            if (c < CC) {
#pragma unroll
                for (int k = 0; k < 8; k++) {
                    int p = p0 + k;
                    if (p < PP) dst[c * PP + p] = acc[j][k];
                }
            }
        }
    }
}

// ---------------- K3: reduce partials; qw = q @ Wsr; qb = q @ bsr ----------
// grid (BB, 7 c-groups), block 128.
__global__ void k_qw(const float* __restrict__ Wsr, const float* __restrict__ bsr) {
    __shared__ __align__(16) float sw[CC * CC];
    __shared__ __align__(16) float sq[7 * PP];
    __shared__ __align__(16) float sb[CC];
    int b = blockIdx.x, cg = blockIdx.y, t = threadIdx.x;
    int c0 = cg * 7;
    for (int e = t; e < CC * CC; e += 128) sw[e] = Wsr[e];
    if (t < CC) sb[t] = bsr[t];
    for (int e = t; e < 7 * PP; e += 128) {
        float s = 0.f;
#pragma unroll
        for (int ic = 0; ic < ICH; ic++)
            s += g_qp[(ic * BB + b) * CC * PP + c0 * PP + e];
        sq[e] = s;
    }
    __syncthreads();
    for (int e = t; e < 7 * CC; e += 128) {
        int j = e / CC, i = e - j * CC;
        float s = 0.f;
#pragma unroll 7
        for (int p = 0; p < CC; p++) s += sq[j * PP + p] * sw[p * CC + i];
        g_qw[b * CC * CC + (c0 + j) * CC + i] = s;
    }
    if (t < 7) {
        float s = 0.f;
#pragma unroll 7
        for (int p = 0; p < CC; p++) s += sq[t * PP + p] * sb[p];
        g_qb[b * CC + c0 + t] = s;
    }
}

// ---------------- K4: max_n of qw @ x (fused) + v = mean_i(x) -------------
// grid (28 n-chunks of 112, BB), block 224.
__global__ void k_attn(const float* __restrict__ x) {
    __shared__ __align__(16) float xt[CC * 112];
    __shared__ __align__(16) float qwsh[CC * CC];
    __shared__ __align__(16) unsigned smax[CC];
    int nc = blockIdx.x, b = blockIdx.y;
    int t = threadIdx.x;  // 224
    for (int e = t; e < CC * CC; e += 224) qwsh[e] = g_qw[b * CC * CC + e];
    if (t < CC) smax[t] = 0u;
    int nb = nc * 112;
    for (int e = t; e < CC * 112; e += 224) {
        int i = e / 112, nn = e - i * 112;
        xt[e] = x[(b * CC + i) * NN + nb + nn];
    }
    __syncthreads();

    // fused v: column mean of the tile (replaces a full extra pass over x)
    if (t < 112) {
        float s = 0.f;
#pragma unroll 7
        for (int i = 0; i < CC; i++) s += xt[i * 112 + t];
        g_v[b * NN + nb + t] = s * (1.f / 49.f);
    }

    int np = t % 28, cg = t / 28;                 // cg in 0..7
    int c0 = (cg == 0) ? 0 : 1 + 6 * cg;          // {0,7,13,19,25,31,37,43}
    int cn = (cg == 0) ? 7 : 6;

    float4 acc[7];
#pragma unroll
    for (int q = 0; q < 7; q++) acc[q] = make_float4(0.f, 0.f, 0.f, 0.f);

#pragma unroll 7
    for (int i = 0; i < CC; i++) {
        float4 xv = *(const float4*)&xt[i * 112 + np * 4];
#pragma unroll
        for (int q = 0; q < 7; q++) {
            if (q < cn) {
                float w = qwsh[(c0 + q) * CC + i];
                acc[q].x += w * xv.x; acc[q].y += w * xv.y;
                acc[q].z += w * xv.z; acc[q].w += w * xv.w;
            }
        }
    }
#pragma unroll
    for (int q = 0; q < 7; q++) {
        if (q < cn) {
            float m = fmaxf(fmaxf(acc[q].x, acc[q].y), fmaxf(acc[q].z, acc[q].w));
            atomicMax(&smax[c0 + q], enc(m));
        }
    }
    __syncthreads();
    if (t < CC) atomicMax(&g_amax[b * CC + t], smax[t]);
}

// ---------------- K5: pv partials = Wproj @ v (split-K, transposed tiles) --
// grid (49 m-tiles of 64, 7 k-splits), block 256. Thread tile 8m x 4b.
__global__ void k_pv(const float* __restrict__ Wp) {
    __shared__ __align__(16) float Wt[32 * 68];    // [nn][mm] pad 68
    __shared__ __align__(16) float Vt[32 * 132];   // [nn][bb] pad 132
    int mt = blockIdx.x, ks = blockIdx.y;
    int t = threadIdx.x;  // 256
    int mb = mt * 64, nb0 = ks * 448;
    int bq = t % 32, mq = t / 32;

    float acc[8][4];
#pragma unroll
    for (int j = 0; j < 8; j++)
#pragma unroll
        for (int k = 0; k < 4; k++) acc[j][k] = 0.f;

    for (int st = 0; st < 14; st++) {
        int nb = nb0 + st * 32;
        __syncthreads();
        for (int e = t; e < 64 * 32; e += 256) {
            int nn = e & 31, mm = e >> 5;
            Wt[nn * 68 + mm] = Wp[(mb + mm) * NN + nb + nn];
        }
        for (int e = t; e < 128 * 32; e += 256) {
            int nn = e & 31, bb = e >> 5;
            Vt[nn * 132 + bb] = g_v[bb * NN + nb + nn];
        }
        __syncthreads();
#pragma unroll 8
        for (int nn = 0; nn < 32; nn++) {
            float4 w0 = *(const float4*)&Wt[nn * 68 + mq * 8];
            float4 w1 = *(const float4*)&Wt[nn * 68 + mq * 8 + 4];
            float4 vv = *(const float4*)&Vt[nn * 132 + bq * 4];
            acc[0][0] += w0.x * vv.x; acc[0][1] += w0.x * vv.y; acc[0][2] += w0.x * vv.z; acc[0][3] += w0.x * vv.w;
            acc[1][0] += w0.y * vv.x; acc[1][1] += w0.y * vv.y; acc[1][2] += w0.y * vv.z; acc[1][3] += w0.y * vv.w;
            acc[2][0] += w0.z * vv.x; acc[2][1] += w0.z * vv.y; acc[2][2] += w0.z * vv.z; acc[2][3] += w0.z * vv.w;
            acc[3][0] += w0.w * vv.x; acc[3][1] += w0.w * vv.y; acc[3][2] += w0.w * vv.z; acc[3][3] += w0.w * vv.w;
            acc[4][0] += w1.x * vv.x; acc[4][1] += w1.x * vv.y; acc[4][2] += w1.x * vv.z; acc[4][3] += w1.x * vv.w;
            acc[5][0] += w1.y * vv.x; acc[5][1] += w1.y * vv.y; acc[5][2] += w1.y * vv.z; acc[5][3] += w1.y * vv.w;
            acc[6][0] += w1.z * vv.x; acc[6][1] += w1.z * vv.y; acc[6][2] += w1.z * vv.z; acc[6][3] += w1.z * vv.w;
            acc[7][0] += w1.w * vv.x; acc[7][1] += w1.w * vv.y; acc[7][2] += w1.w * vv.z; acc[7][3] += w1.w * vv.w;
        }
    }
#pragma unroll
    for (int j = 0; j < 8; j++) {
        float4 o = make_float4(acc[j][0], acc[j][1], acc[j][2], acc[j][3]);
        *(float4*)&g_pvp[(ks * NN + mb + mq * 8 + j) * BB + bq * 4] = o;
    }
}

// ---------------- K6: out[b,m,c] = (sum_ks pvp) * (dec(max)+qb) ------------
__global__ void k_out(float* __restrict__ out) {
    __shared__ __align__(16) float spv[64];
    __shared__ __align__(16) float sat[CC];
    int mt = blockIdx.x, b = blockIdx.y;
    int t = threadIdx.x;  // 256
    if (t < 64) {
        float s = 0.f;
#pragma unroll
        for (int ks = 0; ks < KS; ks++) s += g_pvp[(ks * NN + mt * 64 + t) * BB + b];
        spv[t] = s;
    }
    if (t < CC) sat[t] = dec(g_amax[b * CC + t]) + g_qb[b * CC + t];
    __syncthreads();
    float* base = out + (b * NN + mt * 64) * CC;
    for (int e4 = t; e4 < (64 * CC) / 4; e4 += 256) {
        int e = e4 * 4;
        float4 o;
        o.x = spv[(e + 0) / CC] * sat[(e + 0) % CC];
        o.y = spv[(e + 1) / CC] * sat[(e + 1) % CC];
        o.z = spv[(e + 2) / CC] * sat[(e + 2) % CC];
        o.w = spv[(e + 3) / CC] * sat[(e + 3) % CC];
        *(float4*)(base + e) = o;
    }
}

// ---------------- launch ----------------------------------------------------
extern "C" void kernel_launch(void* const* d_in, const int* in_sizes, int n_in,
                              void* d_out, int out_size) {
    const float* x     = (const float*)d_in[0];
    const float* Wq    = (const float*)d_in[1];
    const float* Wsr   = (const float*)d_in[2];
    const float* bsr   = (const float*)d_in[3];
    const float* Wproj = (const float*)d_in[4];
    float* out = (float*)d_out;

    k_init<<<(BB * CC + 255) / 256, 256>>>();
    k_q<<<dim3(ICH, BB), 96>>>(x, Wq);
    k_qw<<<dim3(BB, 7), 128>>>(Wsr, bsr);
    k_attn<<<dim3(28, BB), 224>>>(x);
    k_pv<<<dim3(49, KS), 256>>>(Wproj);
    k_out<<<dim3(49, BB), 256>>>(out);
}

// round 6
// speedup vs baseline: 1.0050x; 1.0050x over previous
#include <cuda_runtime.h>

#define BB 128
#define CC 49
#define NN 3136
#define PP 49
#define ICH 7
#define KS 7

// ---------------- scratch (device globals; no allocation) ----------------
__device__ float    g_v[BB * NN];               // v[b][n]
__device__ float    g_qp[ICH * BB * CC * PP];   // q partials [ic][b][c*49+p]
__device__ float    g_qw[BB * CC * CC];         // qw[b][c*49+i]
__device__ float    g_qb[BB * CC];              // qb[b][c]
__device__ unsigned g_amax[BB * CC];            // encoded running max
__device__ float    g_pvp[KS * NN * BB];        // pv partials [ks][m][b]

__device__ __forceinline__ unsigned enc(float f) {
    unsigned u = __float_as_uint(f);
    return (u & 0x80000000u) ? ~u : (u | 0x80000000u);
}
__device__ __forceinline__ float dec(unsigned u) {
    return __uint_as_float((u & 0x80000000u) ? (u & 0x7fffffffu) : ~u);
}

// ---------------- K0: reset max accumulators (every replay) ----------------
__global__ void k_init() {
    int t = blockIdx.x * blockDim.x + threadIdx.x;
    if (t < BB * CC) g_amax[t] = 0u;
}

// ---------------- K2: q-conv partials --------------------------------------
// q[b,c,p] = sum_i sum_dd Wq[c,i,dd] * x[b,i,patch(p,dd)]
// grid (ICH, BB), 96 threads; thread tile 4c x 8p. Direct gmem->xpat repack.
__global__ void __launch_bounds__(96, 6)
k_q(const float* __restrict__ x, const float* __restrict__ Wq) {
    __shared__ __align__(16) float xpat[64 * 52 + 8];  // [dd][p], row pad 52
    __shared__ __align__(16) float wt[52 * 65];        // Wq[c][dd] rows pad 65

    int ic = blockIdx.x, b = blockIdx.y;
    int t = threadIdx.x;
    int cc = t % 13, pg = t / 13;        // active when pg < 7 (91 threads)
    int c0 = cc * 4, p0 = pg * 8;

    float acc[4][8];
#pragma unroll
    for (int j = 0; j < 4; j++)
#pragma unroll
        for (int k = 0; k < 8; k++) acc[j][k] = 0.f;

    for (int ii = 0; ii < 7; ii++) {
        int i = ic * 7 + ii;
        __syncthreads();
        // coalesced read of the channel; permuted scatter into [dd][p]
        const float* xc = x + (b * CC + i) * NN;
        for (int e = t; e < NN; e += 96) {
            int y = e / 56, xx = e - y * 56;
            int py = y >> 3, dy = y & 7, px = xx >> 3, dx = xx & 7;
            xpat[(dy * 8 + dx) * 52 + py * 7 + px] = xc[e];
        }
        for (int e = t; e < CC * 64; e += 96) {
            int c = e >> 6, dd = e & 63;
            wt[c * 65 + dd] = Wq[(c * CC + i) * 64 + dd];
        }
        __syncthreads();
        if (pg < 7) {
#pragma unroll 8
            for (int dd = 0; dd < 64; dd++) {
                float4 xa = *(const float4*)&xpat[dd * 52 + p0];
                float4 xb = *(const float4*)&xpat[dd * 52 + p0 + 4];
#pragma unroll
                for (int j = 0; j < 4; j++) {
                    float w = wt[(c0 + j) * 65 + dd];
                    acc[j][0] += w * xa.x; acc[j][1] += w * xa.y;
                    acc[j][2] += w * xa.z; acc[j][3] += w * xa.w;
                    acc[j][4] += w * xb.x; acc[j][5] += w * xb.y;
                    acc[j][6] += w * xb.z; acc[j][7] += w * xb.w;
                }
            }
        }
    }
    if (pg < 7) {
        float* dst = &g_qp[(ic * BB + b) * CC * PP];
#pragma unroll
        for (int j = 0; j < 4; j++) {
            int c = c0 + j;
            if (c < CC) {
#pragma unroll
                for (int k = 0; k < 8; k++) {
                    int p = p0 + k;
                    if (p < PP) dst[c * PP + p] = acc[j][k];
                }
            }
        }
    }
}

// ---------------- K3: reduce partials; qw = q @ Wsr; qb = q @ bsr ----------
// grid (BB, 7 c-groups), block 128.
__global__ void k_qw(const float* __restrict__ Wsr, const float* __restrict__ bsr) {
    __shared__ __align__(16) float sw[CC * CC];
    __shared__ __align__(16) float sq[7 * PP];
    __shared__ __align__(16) float sb[CC];
    int b = blockIdx.x, cg = blockIdx.y, t = threadIdx.x;
    int c0 = cg * 7;
    for (int e = t; e < CC * CC; e += 128) sw[e] = Wsr[e];
    if (t < CC) sb[t] = bsr[t];
    for (int e = t; e < 7 * PP; e += 128) {
        float s = 0.f;
#pragma unroll
        for (int ic = 0; ic < ICH; ic++)
            s += g_qp[(ic * BB + b) * CC * PP + c0 * PP + e];
        sq[e] = s;
    }
    __syncthreads();
    for (int e = t; e < 7 * CC; e += 128) {
        int j = e / CC, i = e - j * CC;
        float s = 0.f;
#pragma unroll 7
        for (int p = 0; p < CC; p++) s += sq[j * PP + p] * sw[p * CC + i];
        g_qw[b * CC * CC + (c0 + j) * CC + i] = s;
    }
    if (t < 7) {
        float s = 0.f;
#pragma unroll 7
        for (int p = 0; p < CC; p++) s += sq[t * PP + p] * sb[p];
        g_qb[b * CC + c0 + t] = s;
    }
}

// ---------------- K4: max_n of qw @ x (fused) + v = mean_i(x) -------------
// grid (28 n-chunks of 112, BB), block 224.
__global__ void k_attn(const float* __restrict__ x) {
    __shared__ __align__(16) float xt[CC * 112];
    __shared__ __align__(16) float qwsh[CC * CC];
    __shared__ __align__(16) unsigned smax[CC];
    int nc = blockIdx.x, b = blockIdx.y;
    int t = threadIdx.x;  // 224
    for (int e = t; e < CC * CC; e += 224) qwsh[e] = g_qw[b * CC * CC + e];
    if (t < CC) smax[t] = 0u;
    int nb = nc * 112;
    for (int e = t; e < CC * 112; e += 224) {
        int i = e / 112, nn = e - i * 112;
        xt[e] = x[(b * CC + i) * NN + nb + nn];
    }
    __syncthreads();

    // fused v: column mean of the tile (replaces a full extra pass over x)
    if (t < 112) {
        float s = 0.f;
#pragma unroll 7
        for (int i = 0; i < CC; i++) s += xt[i * 112 + t];
        g_v[b * NN + nb + t] = s * (1.f / 49.f);
    }

    int np = t % 28, cg = t / 28;                 // cg in 0..7
    int c0 = (cg == 0) ? 0 : 1 + 6 * cg;          // {0,7,13,19,25,31,37,43}
    int cn = (cg == 0) ? 7 : 6;

    float4 acc[7];
#pragma unroll
    for (int q = 0; q < 7; q++) acc[q] = make_float4(0.f, 0.f, 0.f, 0.f);

#pragma unroll 7
    for (int i = 0; i < CC; i++) {
        float4 xv = *(const float4*)&xt[i * 112 + np * 4];
#pragma unroll
        for (int q = 0; q < 7; q++) {
            if (q < cn) {
                float w = qwsh[(c0 + q) * CC + i];
                acc[q].x += w * xv.x; acc[q].y += w * xv.y;
                acc[q].z += w * xv.z; acc[q].w += w * xv.w;
            }
        }
    }
#pragma unroll
    for (int q = 0; q < 7; q++) {
        if (q < cn) {
            float m = fmaxf(fmaxf(acc[q].x, acc[q].y), fmaxf(acc[q].z, acc[q].w));
            atomicMax(&smax[c0 + q], enc(m));
        }
    }
    __syncthreads();
    if (t < CC) atomicMax(&g_amax[b * CC + t], smax[t]);
}

// ---------------- K5: pv partials = Wproj @ v (split-K, transposed tiles) --
// grid (49 m-tiles of 64, 7 k-splits), block 256. Thread tile 8m x 4b.
__global__ void k_pv(const float* __restrict__ Wp) {
    __shared__ __align__(16) float Wt[32 * 68];    // [nn][mm] pad 68
    __shared__ __align__(16) float Vt[32 * 132];   // [nn][bb] pad 132
    int mt = blockIdx.x, ks = blockIdx.y;
    int t = threadIdx.x;  // 256
    int mb = mt * 64, nb0 = ks * 448;
    int bq = t % 32, mq = t / 32;

    float acc[8][4];
#pragma unroll
    for (int j = 0; j < 8; j++)
#pragma unroll
        for (int k = 0; k < 4; k++) acc[j][k] = 0.f;

    for (int st = 0; st < 14; st++) {
        int nb = nb0 + st * 32;
        __syncthreads();
        for (int e = t; e < 64 * 32; e += 256) {
            int nn = e & 31, mm = e >> 5;
            Wt[nn * 68 + mm] = Wp[(mb + mm) * NN + nb + nn];
        }
        for (int e = t; e < 128 * 32; e += 256) {
            int nn = e & 31, bb = e >> 5;
            Vt[nn * 132 + bb] = g_v[bb * NN + nb + nn];
        }
        __syncthreads();
#pragma unroll 8
        for (int nn = 0; nn < 32; nn++) {
            float4 w0 = *(const float4*)&Wt[nn * 68 + mq * 8];
            float4 w1 = *(const float4*)&Wt[nn * 68 + mq * 8 + 4];
            float4 vv = *(const float4*)&Vt[nn * 132 + bq * 4];
            acc[0][0] += w0.x * vv.x; acc[0][1] += w0.x * vv.y; acc[0][2] += w0.x * vv.z; acc[0][3] += w0.x * vv.w;
            acc[1][0] += w0.y * vv.x; acc[1][1] += w0.y * vv.y; acc[1][2] += w0.y * vv.z; acc[1][3] += w0.y * vv.w;
            acc[2][0] += w0.z * vv.x; acc[2][1] += w0.z * vv.y; acc[2][2] += w0.z * vv.z; acc[2][3] += w0.z * vv.w;
            acc[3][0] += w0.w * vv.x; acc[3][1] += w0.w * vv.y; acc[3][2] += w0.w * vv.z; acc[3][3] += w0.w * vv.w;
            acc[4][0] += w1.x * vv.x; acc[4][1] += w1.x * vv.y; acc[4][2] += w1.x * vv.z; acc[4][3] += w1.x * vv.w;
            acc[5][0] += w1.y * vv.x; acc[5][1] += w1.y * vv.y; acc[5][2] += w1.y * vv.z; acc[5][3] += w1.y * vv.w;
            acc[6][0] += w1.z * vv.x; acc[6][1] += w1.z * vv.y; acc[6][2] += w1.z * vv.z; acc[6][3] += w1.z * vv.w;
            acc[7][0] += w1.w * vv.x; acc[7][1] += w1.w * vv.y; acc[7][2] += w1.w * vv.z; acc[7][3] += w1.w * vv.w;
        }
    }
#pragma unroll
    for (int j = 0; j < 8; j++) {
        float4 o = make_float4(acc[j][0], acc[j][1], acc[j][2], acc[j][3]);
        *(float4*)&g_pvp[(ks * NN + mb + mq * 8 + j) * BB + bq * 4] = o;
    }
}

// ---------------- K6: out[b,m,c] = (sum_ks pvp) * (dec(max)+qb) ------------
__global__ void k_out(float* __restrict__ out) {
    __shared__ __align__(16) float spv[64];
    __shared__ __align__(16) float sat[CC];
    int mt = blockIdx.x, b = blockIdx.y;
    int t = threadIdx.x;  // 256
    if (t < 64) {
        float s = 0.f;
#pragma unroll
        for (int ks = 0; ks < KS; ks++) s += g_pvp[(ks * NN + mt * 64 + t) * BB + b];
        spv[t] = s;
    }
    if (t < CC) sat[t] = dec(g_amax[b * CC + t]) + g_qb[b * CC + t];
    __syncthreads();
    float* base = out + (b * NN + mt * 64) * CC;
    for (int e4 = t; e4 < (64 * CC) / 4; e4 += 256) {
        int e = e4 * 4;
        float4 o;
        o.x = spv[(e + 0) / CC] * sat[(e + 0) % CC];
        o.y = spv[(e + 1) / CC] * sat[(e + 1) % CC];
        o.z = spv[(e + 2) / CC] * sat[(e + 2) % CC];
        o.w = spv[(e + 3) / CC] * sat[(e + 3) % CC];
        *(float4*)(base + e) = o;
    }
}

// ---------------- launch ----------------------------------------------------
extern "C" void kernel_launch(void* const* d_in, const int* in_sizes, int n_in,
                              void* d_out, int out_size) {
    const float* x     = (const float*)d_in[0];
    const float* Wq    = (const float*)d_in[1];
    const float* Wsr   = (const float*)d_in[2];
    const float* bsr   = (const float*)d_in[3];
    const float* Wproj = (const float*)d_in[4];
    float* out = (float*)d_out;

    k_init<<<(BB * CC + 255) / 256, 256>>>();
    k_q<<<dim3(ICH, BB), 96>>>(x, Wq);
    k_qw<<<dim3(BB, 7), 128>>>(Wsr, bsr);
    k_attn<<<dim3(28, BB), 224>>>(x);
    k_pv<<<dim3(49, KS), 256>>>(Wproj);
    k_out<<<dim3(49, BB), 256>>>(out);
}